// round 6
// baseline (speedup 1.0000x reference)
#include <cuda_runtime.h>

// CIN forward, fp32 SIMT with packed f32x2 FMA (FFMA2).
// B=512, F0=40, D=32. Layers: (Fh=40,K=1600) -> (Fh=128,K=5120) x2. O=256.
// y[b,d,o] = relu( sum_{f,g} h[b,f,d]*x0[b,g,d]*W[f*40+g,o] + bias[o] )
// split layers: out[:, 0:128] = sum_d y[:,0:128,:], h_next = y[:,128:256,:]
// last layer:   out gets all 256 channels.

#define B_   512
#define F0_  40
#define D_   32
#define O_   256
#define H_   128

typedef unsigned long long u64;

// inter-layer hidden state scratch: h[b][f][d], f in [0,128)
__device__ float g_h1[B_ * H_ * D_];
__device__ float g_h2[B_ * H_ * D_];

__device__ __forceinline__ void fma2(u64 &d, u64 a, u64 b) {
    asm("fma.rn.f32x2 %0, %1, %2, %0;" : "+l"(d) : "l"(a), "l"(b));
}
__device__ __forceinline__ u64 swap2(u64 v) {
    u64 r;
    asm("{\n\t.reg .b32 lo, hi;\n\t"
        "mov.b64 {lo,hi}, %1;\n\t"
        "mov.b64 %0, {hi,lo};\n\t}"
        : "=l"(r) : "l"(v));
    return r;
}
__device__ __forceinline__ float2 unpack2(u64 v) {
    float2 f;
    asm("mov.b64 {%0,%1}, %2;" : "=f"(f.x), "=f"(f.y) : "l"(v));
    return f;
}

// Block: one batch element b. Tile 32(d) x 256(o). 128 threads:
//   og = tid & 31  -> 8 o-values: {og*4..og*4+3} U {128+og*4..128+og*4+3}
//   dg = tid >> 5  -> 8 d-values: dg*8 .. dg*8+7
// Thread tile 8d x 8o, f32x2 over d-pairs, dual accumulators (plain + swapped w)
// to avoid operand duplication.
__global__ void __launch_bounds__(128, 4)
cin_layer(const float* __restrict__ x0,
          const float* __restrict__ W,
          const float* __restrict__ bias,
          float* __restrict__ out,
          int Fh, int split, int out_base, int layer)
{
    __shared__ __align__(16) float hs[H_ * D_];       // h tile  [f][d]
    __shared__ __align__(16) float x0s[F0_ * D_];     // x0 tile [g][d]
    __shared__ __align__(16) float zf[2][F0_ * D_];   // per-f z slab [g][d], dbl buf
    __shared__ float red[4 * O_];

    const float* __restrict__ h =
        (layer == 0) ? x0 : (layer == 1 ? g_h1 : g_h2);
    float* __restrict__ h_next =
        (layer == 0) ? g_h1 : (layer == 1 ? g_h2 : (float*)0);

    const int tid = threadIdx.x;
    const int b   = blockIdx.x;
    const int og  = tid & 31;
    const int dg  = tid >> 5;
    const int d8  = dg * 8;
    const int o4  = og * 4;

    // stage h and x0 into shared
    const int hElems = Fh * D_;
    for (int i = tid; i < hElems; i += 128)
        hs[i] = h[(size_t)b * hElems + i];
    for (int i = tid; i < F0_ * D_; i += 128)
        x0s[i] = x0[(size_t)b * (F0_ * D_) + i];
    __syncthreads();

    // prime z slab for f = 0: zf[idx] = hs[0][d] * x0s[g][d], idx = g*32+d
    #pragma unroll
    for (int j = 0; j < (F0_ * D_) / 128; j++) {
        int idx = tid + j * 128;
        zf[0][idx] = hs[idx & 31] * x0s[idx];
    }
    __syncthreads();

    u64 app[4][4], aps[4][4];
    #pragma unroll
    for (int i = 0; i < 4; i++)
        #pragma unroll
        for (int j = 0; j < 4; j++) { app[i][j] = 0ull; aps[i][j] = 0ull; }

    int buf = 0;
    for (int f = 0; f < Fh; f++) {
        // prefetch z slab for f+1 into the other buffer (overlapped, synced below)
        if (f + 1 < Fh) {
            #pragma unroll
            for (int j = 0; j < (F0_ * D_) / 128; j++) {
                int idx = tid + j * 128;
                zf[buf ^ 1][idx] = hs[(f + 1) * D_ + (idx & 31)] * x0s[idx];
            }
        }

        // W row base for k = f*F0 (+g below). Row = 256 floats = 64 ulonglong2.
        const ulonglong2* __restrict__ wp =
            reinterpret_cast<const ulonglong2*>(W) + (size_t)(f * F0_) * (O_ / 4) + og;
        const ulonglong2* zp =
            reinterpret_cast<const ulonglong2*>(zf[buf]) + dg * 2;

        #pragma unroll 4
        for (int g = 0; g < F0_; g++) {
            ulonglong2 a01 = zp[g * 8];       // z[d8..d8+3] as 2 f32x2 pairs
            ulonglong2 a23 = zp[g * 8 + 1];   // z[d8+4..d8+7]
            ulonglong2 wA  = wp[(size_t)g * 64];        // W[k][o4..o4+3]
            ulonglong2 wB  = wp[(size_t)g * 64 + 32];   // W[k][128+o4..+3]
            u64 av[4] = { a01.x, a01.y, a23.x, a23.y };
            u64 wv[4] = { wA.x, wA.y, wB.x, wB.y };
            u64 sv[4] = { swap2(wA.x), swap2(wA.y), swap2(wB.x), swap2(wB.y) };
            #pragma unroll
            for (int dp = 0; dp < 4; dp++)
                #pragma unroll
                for (int q = 0; q < 4; q++) {
                    fma2(app[dp][q], av[dp], wv[q]);   // (a_e * w_e)
                    fma2(aps[dp][q], av[dp], sv[q]);   // (a_e * w_{1-e})
                }
        }
        __syncthreads();
        buf ^= 1;
    }

    // unpack accumulators: y[local d 0..7][local o 0..7]
    //   local o l: l<4 -> o4+l ; l>=4 -> 128+o4+(l-4)
    float y[8][8];
    #pragma unroll
    for (int dp = 0; dp < 4; dp++)
        #pragma unroll
        for (int q = 0; q < 4; q++) {
            float2 pp = unpack2(app[dp][q]);
            float2 ps = unpack2(aps[dp][q]);
            y[2 * dp    ][2 * q    ] = pp.x;
            y[2 * dp + 1][2 * q + 1] = pp.y;
            y[2 * dp    ][2 * q + 1] = ps.x;
            y[2 * dp + 1][2 * q    ] = ps.y;
        }

    // bias + relu
    float bi[8];
    #pragma unroll
    for (int lj = 0; lj < 8; lj++) {
        int oglob = (lj < 4) ? (o4 + lj) : (H_ + o4 + (lj - 4));
        bi[lj] = __ldg(&bias[oglob]);
    }
    #pragma unroll
    for (int li = 0; li < 8; li++)
        #pragma unroll
        for (int lj = 0; lj < 8; lj++) {
            float v = y[li][lj] + bi[lj];
            y[li][lj] = v > 0.f ? v : 0.f;
        }

    // per-thread partial sum over its 8 d, then cross-dg reduce in smem
    #pragma unroll
    for (int lj = 0; lj < 8; lj++) {
        float s = 0.f;
        #pragma unroll
        for (int li = 0; li < 8; li++) s += y[li][lj];
        int oglob = (lj < 4) ? (o4 + lj) : (H_ + o4 + (lj - 4));
        red[dg * O_ + oglob] = s;
    }
    __syncthreads();

    for (int o = tid; o < O_; o += 128) {
        float s = red[o] + red[O_ + o] + red[2 * O_ + o] + red[3 * O_ + o];
        if (split) {
            if (o < H_) out[(size_t)b * 512 + out_base + o] = s;
        } else {
            out[(size_t)b * 512 + out_base + o] = s;
        }
    }

    // write next-layer h (channels 128..255, post-relu), layout h[b][f][d]
    if (split && h_next) {
        #pragma unroll
        for (int lj = 4; lj < 8; lj++) {
            int fn = o4 + (lj - 4);
            float4 v0 = make_float4(y[0][lj], y[1][lj], y[2][lj], y[3][lj]);
            float4 v1 = make_float4(y[4][lj], y[5][lj], y[6][lj], y[7][lj]);
            float4* dst = reinterpret_cast<float4*>(
                h_next + ((size_t)b * H_ + fn) * D_ + d8);
            dst[0] = v0;
            dst[1] = v1;
        }
    }
}

extern "C" void kernel_launch(void* const* d_in, const int* in_sizes, int n_in,
                              void* d_out, int out_size) {
    const float* x  = (const float*)d_in[0];
    const float* W1 = (const float*)d_in[1];
    const float* b1 = (const float*)d_in[2];
    const float* W2 = (const float*)d_in[3];
    const float* b2 = (const float*)d_in[4];
    const float* W3 = (const float*)d_in[5];
    const float* b3 = (const float*)d_in[6];
    float* out = (float*)d_out;

    cin_layer<<<B_, 128>>>(x, W1, b1, out, F0_, 1, 0,   0);
    cin_layer<<<B_, 128>>>(x, W2, b2, out, H_,  1, H_,  1);
    cin_layer<<<B_, 128>>>(x, W3, b3, out, H_,  0, 2 * H_, 2);
}

// round 8
// speedup vs baseline: 1.0620x; 1.0620x over previous
#include <cuda_runtime.h>
#include <cstdint>

// CIN forward, fp32 SIMT, FFMA2, W staged via cp.async double-buffered chunks.
// B=512, F0=40, D=32. Layers: (Fh=40,K=1600) -> (Fh=128,K=5120) x2. O=256.

#define B_   512
#define F0_  40
#define D_   32
#define O_   256
#define H_   128

typedef unsigned long long u64;

__device__ float g_h1[B_ * H_ * D_];
__device__ float g_h2[B_ * H_ * D_];

__device__ __forceinline__ void fma2(u64 &d, u64 a, u64 b) {
    asm("fma.rn.f32x2 %0, %1, %2, %0;" : "+l"(d) : "l"(a), "l"(b));
}
__device__ __forceinline__ u64 swap2(u64 v) {
    u64 r;
    asm("{\n\t.reg .b32 lo, hi;\n\t"
        "mov.b64 {lo,hi}, %1;\n\t"
        "mov.b64 %0, {hi,lo};\n\t}"
        : "=l"(r) : "l"(v));
    return r;
}
__device__ __forceinline__ float2 unpack2(u64 v) {
    float2 f;
    asm("mov.b64 {%0,%1}, %2;" : "=f"(f.x), "=f"(f.y) : "l"(v));
    return f;
}
__device__ __forceinline__ uint32_t s2u(const void* p) {
    uint32_t a;
    asm("{ .reg .u64 t; cvta.to.shared.u64 t, %1; cvt.u32.u64 %0, t; }"
        : "=r"(a) : "l"(p));
    return a;
}
__device__ __forceinline__ void cpa16(uint32_t dst, const float* src) {
    asm volatile("cp.async.ca.shared.global [%0], [%1], 16;"
                 :: "r"(dst), "l"(src));
}
#define CP_COMMIT() asm volatile("cp.async.commit_group;")
#define CP_WAIT0()  asm volatile("cp.async.wait_group 0;")

// Block: one batch b. Tile 32(d) x 256(o), 128 threads, thread tile 8d x 8o.
// W streamed in 8-row (8KB) chunks: prev chunk computes while next transfers.
__global__ void __launch_bounds__(128, 4)
cin_layer(const float* __restrict__ x0,
          const float* __restrict__ W,
          const float* __restrict__ bias,
          float* __restrict__ out,
          int Fh, int split, int out_base, int layer)
{
    __shared__ __align__(16) float hs[H_ * D_];       // 16 KB
    __shared__ __align__(16) float x0s[F0_ * D_];     //  5 KB
    __shared__ __align__(16) float zf[2][F0_ * D_];   // 10 KB (aliased as red later)
    __shared__ __align__(16) float Wb[2][8 * O_];     // 16 KB, W chunk dbl-buf
    float* red = (float*)zf;                          // epilogue reduce scratch

    const float* __restrict__ h =
        (layer == 0) ? x0 : (layer == 1 ? g_h1 : g_h2);
    float* __restrict__ h_next =
        (layer == 0) ? g_h1 : (layer == 1 ? g_h2 : (float*)0);

    const int tid = threadIdx.x;
    const int b   = blockIdx.x;
    const int og  = tid & 31;
    const int dg  = tid >> 5;
    const int d8  = dg * 8;
    const int o4  = og * 4;

    const uint32_t wsm = s2u(Wb) + tid * 16;   // this thread's staging base
    const int nch = Fh * 5;                    // 8-row chunks (40 g = 5 chunks/f)

    // prime W chunk 0 into Wb[0] (overlaps with hs/x0s staging below)
    {
        const float* src = W + tid * 4;
        #pragma unroll
        for (int u = 0; u < 4; u++) cpa16(wsm + u * 2048, src + u * 512);
    }
    CP_COMMIT();

    // stage h and x0 into shared
    const int hElems = Fh * D_;
    for (int i = tid; i < hElems; i += 128)
        hs[i] = h[(size_t)b * hElems + i];
    for (int i = tid; i < F0_ * D_; i += 128)
        x0s[i] = x0[(size_t)b * (F0_ * D_) + i];
    __syncthreads();

    // z slab for f = 0 (visible to all at first chunk barrier)
    #pragma unroll
    for (int j = 0; j < (F0_ * D_) / 128; j++) {
        int idx = tid + j * 128;
        zf[0][idx] = hs[idx & 31] * x0s[idx];
    }

    u64 app[4][4], aps[4][4];
    #pragma unroll
    for (int i = 0; i < 4; i++)
        #pragma unroll
        for (int j = 0; j < 4; j++) { app[i][j] = 0ull; aps[i][j] = 0ull; }

    int wb = 0, zb = 0;
    for (int f = 0; f < Fh; f++) {
        const ulonglong2* zp =
            reinterpret_cast<const ulonglong2*>(zf[zb]) + dg * 2;

        for (int c = 0; c < 5; c++) {
            CP_WAIT0();        // chunk (f,c) landed (this thread's group)
            __syncthreads();   // chunk visible to all; all warps done w/ other buf

            // z slab for f+1, once per f, after the barrier (race-free)
            if (c == 0 && f + 1 < Fh) {
                #pragma unroll
                for (int j = 0; j < (F0_ * D_) / 128; j++) {
                    int idx = tid + j * 128;
                    zf[zb ^ 1][idx] = hs[(f + 1) * D_ + (idx & 31)] * x0s[idx];
                }
            }

            // kick off next chunk into the other buffer (safe: post-barrier)
            int kn = f * 5 + c + 1;
            if (kn < nch) {
                const float* src = W + (size_t)kn * 2048 + tid * 4;
                uint32_t dst = wsm + (wb ^ 1) * 8192;
                #pragma unroll
                for (int u = 0; u < 4; u++) cpa16(dst + u * 2048, src + u * 512);
            }
            CP_COMMIT();

            // compute 8 g-rows from Wb[wb]
            const int g0 = c * 8;
            #pragma unroll
            for (int r = 0; r < 8; r++) {
                const int g = g0 + r;
                ulonglong2 a01 = zp[g * 8];       // z[d8..d8+3]
                ulonglong2 a23 = zp[g * 8 + 1];   // z[d8+4..d8+7]
                ulonglong2 wA  = *reinterpret_cast<const ulonglong2*>(
                    &Wb[wb][r * O_ + o4]);        // W[k][o4..o4+3]
                ulonglong2 wB  = *reinterpret_cast<const ulonglong2*>(
                    &Wb[wb][r * O_ + H_ + o4]);   // W[k][128+o4..+3]
                u64 av[4] = { a01.x, a01.y, a23.x, a23.y };
                u64 wv[4] = { wA.x, wA.y, wB.x, wB.y };
                u64 sv[4] = { swap2(wA.x), swap2(wA.y), swap2(wB.x), swap2(wB.y) };
                #pragma unroll
                for (int dp = 0; dp < 4; dp++)
                    #pragma unroll
                    for (int q = 0; q < 4; q++) {
                        fma2(app[dp][q], av[dp], wv[q]);
                        fma2(aps[dp][q], av[dp], sv[q]);
                    }
            }
            wb ^= 1;
        }
        zb ^= 1;
    }
    __syncthreads();   // all zf reads done before red alias is written

    // unpack accumulators: y[local d 0..7][local o 0..7]
    float y[8][8];
    #pragma unroll
    for (int dp = 0; dp < 4; dp++)
        #pragma unroll
        for (int q = 0; q < 4; q++) {
            float2 pp = unpack2(app[dp][q]);
            float2 ps = unpack2(aps[dp][q]);
            y[2 * dp    ][2 * q    ] = pp.x;
            y[2 * dp + 1][2 * q + 1] = pp.y;
            y[2 * dp    ][2 * q + 1] = ps.x;
            y[2 * dp + 1][2 * q    ] = ps.y;
        }

    // bias + relu
    float bi[8];
    #pragma unroll
    for (int lj = 0; lj < 8; lj++) {
        int oglob = (lj < 4) ? (o4 + lj) : (H_ + o4 + (lj - 4));
        bi[lj] = __ldg(&bias[oglob]);
    }
    #pragma unroll
    for (int li = 0; li < 8; li++)
        #pragma unroll
        for (int lj = 0; lj < 8; lj++) {
            float v = y[li][lj] + bi[lj];
            y[li][lj] = v > 0.f ? v : 0.f;
        }

    // per-thread partial sum over its 8 d, then cross-dg reduce in smem
    #pragma unroll
    for (int lj = 0; lj < 8; lj++) {
        float s = 0.f;
        #pragma unroll
        for (int li = 0; li < 8; li++) s += y[li][lj];
        int oglob = (lj < 4) ? (o4 + lj) : (H_ + o4 + (lj - 4));
        red[dg * O_ + oglob] = s;
    }
    __syncthreads();

    for (int o = tid; o < O_; o += 128) {
        float s = red[o] + red[O_ + o] + red[2 * O_ + o] + red[3 * O_ + o];
        if (split) {
            if (o < H_) out[(size_t)b * 512 + out_base + o] = s;
        } else {
            out[(size_t)b * 512 + out_base + o] = s;
        }
    }

    // next-layer h (channels 128..255, post-relu), layout h[b][f][d]
    if (split && h_next) {
        #pragma unroll
        for (int lj = 4; lj < 8; lj++) {
            int fn = o4 + (lj - 4);
            float4 v0 = make_float4(y[0][lj], y[1][lj], y[2][lj], y[3][lj]);
            float4 v1 = make_float4(y[4][lj], y[5][lj], y[6][lj], y[7][lj]);
            float4* dst = reinterpret_cast<float4*>(
                h_next + ((size_t)b * H_ + fn) * D_ + d8);
            dst[0] = v0;
            dst[1] = v1;
        }
    }
}

extern "C" void kernel_launch(void* const* d_in, const int* in_sizes, int n_in,
                              void* d_out, int out_size) {
    const float* x  = (const float*)d_in[0];
    const float* W1 = (const float*)d_in[1];
    const float* b1 = (const float*)d_in[2];
    const float* W2 = (const float*)d_in[3];
    const float* b2 = (const float*)d_in[4];
    const float* W3 = (const float*)d_in[5];
    const float* b3 = (const float*)d_in[6];
    float* out = (float*)d_out;

    cin_layer<<<B_, 128>>>(x, W1, b1, out, F0_, 1, 0,      0);
    cin_layer<<<B_, 128>>>(x, W2, b2, out, H_,  1, H_,     1);
    cin_layer<<<B_, 128>>>(x, W3, b3, out, H_,  0, 2 * H_, 2);
}